// round 11
// baseline (speedup 1.0000x reference)
#include <cuda_runtime.h>
#include <math.h>

#define T_LEN      220500
#define NCH        64
#define CHUNK      84
#define NCHUNK_CH  2625                // 220500 / 84
#define NCHUNK_TOT 168000              // 64 * 2625
#define TOTAL_F4   3528000             // 14,112,000 / 4
#define BT         128
#define NW         (BT / 32)
#define TILE       (BT * CHUNK)        // 10752 floats = 43008 B
#define F4PB       (TILE / 4)          // 2688
#define NBLK       ((NCHUNK_TOT + BT - 1) / BT)   // 1313
#define WIN        24                  // reset blocks occur every 20-21 blocks

typedef unsigned long long u64;

// ---- packed f32x2 helpers (sm_103a FFMA2 path) ----
__device__ __forceinline__ u64 fma2(u64 a, u64 b, u64 c) {
    u64 d; asm("fma.rn.f32x2 %0, %1, %2, %3;" : "=l"(d) : "l"(a), "l"(b), "l"(c)); return d;
}
__device__ __forceinline__ u64 mul2(u64 a, u64 b) {
    u64 d; asm("mul.rn.f32x2 %0, %1, %2;" : "=l"(d) : "l"(a), "l"(b)); return d;
}
__device__ __forceinline__ u64 pack2(float lo, float hi) {
    u64 d; asm("mov.b64 %0, {%1, %2};" : "=l"(d) : "f"(lo), "f"(hi)); return d;
}
__device__ __forceinline__ void unpack2(u64 v, float& lo, float& hi) {
    asm("mov.b64 {%0, %1}, %2;" : "=f"(lo), "=f"(hi) : "l"(v));
}

// published per-block aggregate: [0]=(La,Lb,Lc,Ld) [1]=(Lp,Lq,Hp,Hq) [2]=(Ha,Hb,Hc,Hd)
__device__ float4 g_agg[NBLK][3];
__device__ int    g_flag[NBLK];

struct Map { float a, b, c, d, p, q; };   // s -> [a b; c d] s + (p,q)

__device__ __forceinline__ Map mapIdent() { Map m = {1.f,0.f,0.f,1.f,0.f,0.f}; return m; }
// hi applied AFTER lo
__device__ __forceinline__ Map mapCompose(const Map& hi, const Map& lo) {
    Map r;
    r.a = fmaf(hi.a, lo.a, hi.b * lo.c);
    r.b = fmaf(hi.a, lo.b, hi.b * lo.d);
    r.c = fmaf(hi.c, lo.a, hi.d * lo.c);
    r.d = fmaf(hi.c, lo.b, hi.d * lo.d);
    r.p = fmaf(hi.a, lo.p, fmaf(hi.b, lo.q, hi.p));
    r.q = fmaf(hi.c, lo.p, fmaf(hi.d, lo.q, hi.q));
    return r;
}
__device__ __forceinline__ float2 mapApply(const Map& m, float vx, float vy) {
    return make_float2(fmaf(m.a, vx, fmaf(m.b, vy, m.p)),
                       fmaf(m.c, vx, fmaf(m.d, vy, m.q)));
}
__device__ __forceinline__ Map mapShflUp(const Map& m, int d) {
    Map r;
    r.a = __shfl_up_sync(0xffffffffu, m.a, d);
    r.b = __shfl_up_sync(0xffffffffu, m.b, d);
    r.c = __shfl_up_sync(0xffffffffu, m.c, d);
    r.d = __shfl_up_sync(0xffffffffu, m.d, d);
    r.p = __shfl_up_sync(0xffffffffu, m.p, d);
    r.q = __shfl_up_sync(0xffffffffu, m.q, d);
    return r;
}

__global__ void init_kernel() {
    int i = blockIdx.x * blockDim.x + threadIdx.x;
    if (i < NBLK) g_flag[i] = 0;
}

// packed biquad step (both filters in one f32x2 lane pair): y0 = yL - yH
#define BSTEP2(xk, ok) {                                         \
    u64 xk2 = pack2((xk), (xk));                                 \
    u64 ff  = fma2(cb0, xk2, fma2(cb1, xm1p, mul2(cb2, xm2p))); \
    u64 yy  = fma2(cn1, s1p, fma2(cn2, s2p, ff));                \
    float yL, yH; unpack2(yy, yL, yH);                           \
    (ok) = yL - yH;                                              \
    s2p = s1p; s1p = yy; xm2p = xm1p; xm1p = xk2; }

// data-parallel correction of one sample: y = y0 + uL*s1 + vL*s2 + uH*ns3 + vH*ns4
#define CORR(y0v, uLv, vLv, uHv, vHv, st) \
    fmaf((vHv), (st).w, fmaf((uHv), (st).z, fmaf((vLv), (st).y, fmaf((uLv), (st).x, (y0v)))))

__global__ __launch_bounds__(BT, 5)
void fused_kernel(const float* __restrict__ x, float* __restrict__ out,
                  const int* __restrict__ sr_p,
                  const float* __restrict__ cl_p,
                  const float* __restrict__ ch_p) {
    __shared__ float  sbuf[TILE];
    __shared__ float  scoef[10];
    __shared__ __align__(16) float2 stabA[CHUNK];   // (uL[n], uH[n]) — 16B aligned for LDS.128
    __shared__ __align__(16) float2 stabB[CHUNK];   // (vL[n], vH[n])
    __shared__ float4 sState[BT];        // per-chunk (sL1, sL2, -sH1, -sH2)
    __shared__ Map    sWarpL[NW], sWarpH[NW], sExclL[NW], sExclH[NW];
    __shared__ float4 sPred[WIN][3];
    __shared__ float4 sVin;

    int t   = threadIdx.x;
    int bid = blockIdx.x;

    // ---- stage tile coalesced ----
    size_t base4 = (size_t)bid * F4PB;
    const float4* xg4 = (const float4*)x;
    float4* s4 = (float4*)sbuf;
#pragma unroll
    for (int i = 0; i < F4PB / BT; i++) {
        size_t idx = base4 + t + (size_t)i * BT;
        if (idx < TOTAL_F4) s4[t + i * BT] = xg4[idx];
    }

    // ---- thread 0: coefficients ----
    if (t == 0) {
        int iv = *sr_p;
        float sr = (iv > 0 && iv < 100000000) ? (float)iv : __int_as_float(iv);
        const float Q = 0.707f;
        {
            float w0 = 2.0f * 3.14159265358979323846f * (*cl_p) / sr;
            float c  = cosf(w0);
            float al = sinf(w0) / (2.0f * Q);
            float a0 = 1.0f + al;
            scoef[0] = ((1.0f - c) * 0.5f) / a0;
            scoef[1] = (1.0f - c) / a0;
            scoef[2] = scoef[0];
            scoef[3] = (-2.0f * c) / a0;
            scoef[4] = (1.0f - al) / a0;
        }
        {
            float w0 = 2.0f * 3.14159265358979323846f * (*ch_p) / sr;
            float c  = cosf(w0);
            float al = sinf(w0) / (2.0f * Q);
            float a0 = 1.0f + al;
            scoef[5] = ((1.0f + c) * 0.5f) / a0;
            scoef[6] = -(1.0f + c) / a0;
            scoef[7] = scoef[5];
            scoef[8] = (-2.0f * c) / a0;
            scoef[9] = (1.0f - al) / a0;
        }
    }
    __syncthreads();

    float bL0 = scoef[0], bL1 = scoef[1], bL2 = scoef[2];
    float nL1 = -scoef[3], nL2 = -scoef[4];
    float bH0 = scoef[5], bH1 = scoef[6], bH2 = scoef[7];
    float nH1 = -scoef[8], nH2 = -scoef[9];

    // packed coefficient pairs (L in lane0, H in lane1)
    u64 cb0 = pack2(bL0, bH0), cb1 = pack2(bL1, bH1), cb2 = pack2(bL2, bH2);
    u64 cn1 = pack2(nL1, nH1), cn2 = pack2(nL2, nH2);

    int  g       = bid * BT + t;
    bool valid   = g < NCHUNK_TOT;
    bool resetCk = valid && (g % NCHUNK_CH) == 0;   // chunk is channel start

    // FIR history — must be read by ALL threads before pass A overwrites smem
    float hx1 = 0.f, hx2 = 0.f;
    if (valid && !resetCk) {
        if (t == 0) {
            size_t s0 = (size_t)g * CHUNK;
            hx1 = x[s0 - 1];
            hx2 = x[s0 - 2];
        } else {
            hx1 = sbuf[t * CHUNK - 1];
            hx2 = sbuf[t * CHUNK - 2];
        }
    }
    __syncthreads();   // history reads complete before in-place y0 writes

    // ---- homogeneous basis tables (threads 0-3), overlapped with pass A ----
    // t=0: uL -> stabA[n].x ; t=1: vL -> stabB[n].x
    // t=2: uH -> stabA[n].y ; t=3: vH -> stabB[n].y
    if (t < 4) {
        float na1 = (t < 2) ? nL1 : nH1;
        float na2 = (t < 2) ? nL2 : nH2;
        float y1 = (t & 1) ? 0.f : 1.f;
        float y2 = (t & 1) ? 1.f : 0.f;
        float* dst = (t & 1) ? (float*)stabB : (float*)stabA;
        dst += (t >> 1);   // .x or .y
#pragma unroll 1
        for (int n = 0; n < CHUNK; n++) {
            float y = fmaf(na1, y1, na2 * y2);
            dst[n * 2] = y;
            y2 = y1; y1 = y;
        }
    }

    // ---- pass A: zero-init packed recurrence, write y0 in place ----
    float l1, l2, h1, h2;
    {
        u64 s1p = pack2(0.f, 0.f), s2p = s1p;
        u64 xm1p = pack2(hx1, hx1), xm2p = pack2(hx2, hx2);
        if (valid) {
            float* cb = sbuf + t * CHUNK;
            float4 xv = *reinterpret_cast<const float4*>(cb);
#pragma unroll 1
            for (int k = 0; k < CHUNK - 4; k += 4) {
                float4 nx = *reinterpret_cast<const float4*>(cb + k + 4);
                float4 ov;
                BSTEP2(xv.x, ov.x);
                BSTEP2(xv.y, ov.y);
                BSTEP2(xv.z, ov.z);
                BSTEP2(xv.w, ov.w);
                *reinterpret_cast<float4*>(cb + k) = ov;
                xv = nx;
            }
            float4 ov;
            BSTEP2(xv.x, ov.x);
            BSTEP2(xv.y, ov.y);
            BSTEP2(xv.z, ov.z);
            BSTEP2(xv.w, ov.w);
            *reinterpret_cast<float4*>(cb + CHUNK - 4) = ov;
        }
        unpack2(s1p, l1, h1);
        unpack2(s2p, l2, h2);
    }
    __syncthreads();

    // A^CHUNK matrix entries from the basis tables
    float2 a83 = stabA[CHUNK - 1], b83 = stabB[CHUNK - 1];
    float2 a82 = stabA[CHUNK - 2], b82 = stabB[CHUNK - 2];

    // ---- per-chunk affine maps (interleaved L/H scan) ----
    Map mL, mH;
    if (!valid) { mL = mapIdent(); mH = mapIdent(); }
    else if (resetCk) {
        mL.a = mL.b = mL.c = mL.d = 0.f; mL.p = l1; mL.q = l2;
        mH.a = mH.b = mH.c = mH.d = 0.f; mH.p = h1; mH.q = h2;
    } else {
        mL.a = a83.x; mL.b = b83.x; mL.c = a82.x; mL.d = b82.x; mL.p = l1; mL.q = l2;
        mH.a = a83.y; mH.b = b83.y; mH.c = a82.y; mH.d = b82.y; mH.p = h1; mH.q = h2;
    }

    int lane = t & 31, w = t >> 5;
#pragma unroll
    for (int off = 1; off < 32; off <<= 1) {
        Map pL = mapShflUp(mL, off);
        Map pH = mapShflUp(mH, off);
        if (lane >= off) { mL = mapCompose(mL, pL); mH = mapCompose(mH, pH); }
    }
    if (lane == 31) { sWarpL[w] = mL; sWarpH[w] = mH; }
    __syncthreads();

    // ---- block aggregate + IMMEDIATE publish ----
    if (t == 0) {
        Map eL = mapIdent(), eH = mapIdent();
#pragma unroll
        for (int i = 0; i < NW; i++) {
            sExclL[i] = eL; sExclH[i] = eH;
            eL = mapCompose(sWarpL[i], eL);
            eH = mapCompose(sWarpH[i], eH);
        }
        __stcg(&g_agg[bid][0], make_float4(eL.a, eL.b, eL.c, eL.d));
        __stcg(&g_agg[bid][1], make_float4(eL.p, eL.q, eH.p, eH.q));
        __stcg(&g_agg[bid][2], make_float4(eH.a, eH.b, eH.c, eH.d));
        __threadfence();
        atomicExch(&g_flag[bid], 1);
    }

    // ---- parallel-window look-back (warp 0) ----
    if (w == 0) {
        int pred = bid - 1 - t;
        if (t < WIN && pred >= 0) {
            while (__ldcg(&g_flag[pred]) == 0) __nanosleep(64);
            __threadfence();
            sPred[t][0] = __ldcg(&g_agg[pred][0]);
            sPred[t][1] = __ldcg(&g_agg[pred][1]);
            sPred[t][2] = __ldcg(&g_agg[pred][2]);
        }
        __syncwarp();
        if (t == 0) {
            float4 vin = make_float4(0.f, 0.f, 0.f, 0.f);
            if (bid > 0) {
                int nAvail = (bid < WIN) ? bid : WIN;
                int term = nAvail - 1;
                for (int i = 0; i < nAvail; i++) {
                    float4 fL = sPred[i][0];
                    float4 fH = sPred[i][2];
                    if (fL.x == 0.f && fL.y == 0.f && fL.z == 0.f && fL.w == 0.f &&
                        fH.x == 0.f && fH.y == 0.f && fH.z == 0.f && fH.w == 0.f) {
                        term = i;
                        break;
                    }
                }
                float4 off0 = sPred[term][1];
                float sLx = off0.x, sLy = off0.y, sHx = off0.z, sHy = off0.w;
                for (int i = term - 1; i >= 0; i--) {
                    float4 fL = sPred[i][0];
                    float4 fH = sPred[i][2];
                    float4 fo = sPred[i][1];
                    float nLx = fmaf(fL.x, sLx, fmaf(fL.y, sLy, fo.x));
                    float nLy = fmaf(fL.z, sLx, fmaf(fL.w, sLy, fo.y));
                    float nHx = fmaf(fH.x, sHx, fmaf(fH.y, sHy, fo.z));
                    float nHy = fmaf(fH.z, sHx, fmaf(fH.w, sHy, fo.w));
                    sLx = nLx; sLy = nLy; sHx = nHx; sHy = nHy;
                }
                vin = make_float4(sLx, sLy, sHx, sHy);
            }
            sVin = vin;
        }
    }
    __syncthreads();
    float4 vin = sVin;

    // thread-exclusive map within block
    Map exL = mapShflUp(mL, 1);
    Map exH = mapShflUp(mH, 1);
    if (lane == 0) { exL = mapIdent(); exH = mapIdent(); }
    exL = mapCompose(exL, sExclL[w]);
    exH = mapCompose(exH, sExclH[w]);

    // exact initial state for this chunk; publish pre-negated H for FMA-only corr
    {
        float2 sL = resetCk ? make_float2(0.f, 0.f) : mapApply(exL, vin.x, vin.y);
        float2 sH = resetCk ? make_float2(0.f, 0.f) : mapApply(exH, vin.z, vin.w);
        sState[t] = make_float4(sL.x, sL.y, -sH.x, -sH.y);
    }
    __syncthreads();

    // ---- fused correction + coalesced store (data-parallel, no chain) ----
    const float4* qA = (const float4*)stabA;   // qA[j] = (uL,uH,uL,uH) @ n=2j,2j+1
    const float4* qB = (const float4*)stabB;
    float4* og4 = (float4*)out;
#pragma unroll
    for (int i = 0; i < F4PB / BT; i++) {
        int idx4 = t + i * BT;
        size_t gidx = base4 + idx4;
        if (gidx < TOTAL_F4) {
            int flat = idx4 * 4;                  // sample index within tile
            int c    = flat / CHUNK;              // local chunk id
            int n    = flat - c * CHUNK;          // sample phase (multiple of 4)
            float4 y0 = s4[idx4];
            float4 st = sState[c];
            float4 A0 = qA[n >> 1];               // uL,uH @ n, n+1
            float4 A1 = qA[(n >> 1) + 1];         // uL,uH @ n+2, n+3
            float4 B0 = qB[n >> 1];
            float4 B1 = qB[(n >> 1) + 1];
            float4 yv;
            yv.x = CORR(y0.x, A0.x, B0.x, A0.y, B0.y, st);
            yv.y = CORR(y0.y, A0.z, B0.z, A0.w, B0.w, st);
            yv.z = CORR(y0.z, A1.x, B1.x, A1.y, B1.y, st);
            yv.w = CORR(y0.w, A1.z, B1.z, A1.w, B1.w, st);
            og4[gidx] = yv;
        }
    }
}

extern "C" void kernel_launch(void* const* d_in, const int* in_sizes, int n_in,
                              void* d_out, int out_size) {
    const float* audio = (const float*)d_in[0];
    const int*   sr    = (const int*)d_in[1];
    const float* cl    = (const float*)d_in[2];
    const float* ch    = (const float*)d_in[3];
    float* out = (float*)d_out;

    init_kernel<<<(NBLK + 255) / 256, 256>>>();
    fused_kernel<<<NBLK, BT>>>(audio, out, sr, cl, ch);
}

// round 12
// speedup vs baseline: 1.3346x; 1.3346x over previous
#include <cuda_runtime.h>
#include <math.h>

#define T_LEN      220500
#define NCH        64
#define CHUNK      84
#define NCHUNK_CH  2625                // 220500 / 84
#define NCHUNK_TOT 168000              // 64 * 2625
#define TOTAL_F4   3528000             // 14,112,000 / 4
#define BT         128
#define NW         (BT / 32)
#define TILE       (BT * CHUNK)        // 10752 floats = 43008 B
#define F4PB       (TILE / 4)          // 2688
#define NBLK       ((NCHUNK_TOT + BT - 1) / BT)   // 1313
#define WIN        24                  // reset blocks occur every 20-21 blocks

typedef unsigned long long u64;

// ---- packed f32x2 helpers (sm_103a FFMA2 path) ----
__device__ __forceinline__ u64 fma2(u64 a, u64 b, u64 c) {
    u64 d; asm("fma.rn.f32x2 %0, %1, %2, %3;" : "=l"(d) : "l"(a), "l"(b), "l"(c)); return d;
}
__device__ __forceinline__ u64 mul2(u64 a, u64 b) {
    u64 d; asm("mul.rn.f32x2 %0, %1, %2;" : "=l"(d) : "l"(a), "l"(b)); return d;
}
__device__ __forceinline__ u64 pack2(float lo, float hi) {
    u64 d; asm("mov.b64 %0, {%1, %2};" : "=l"(d) : "f"(lo), "f"(hi)); return d;
}
__device__ __forceinline__ void unpack2(u64 v, float& lo, float& hi) {
    asm("mov.b64 {%0, %1}, %2;" : "=f"(lo), "=f"(hi) : "l"(v));
}

// published per-block aggregate: [0]=(La,Lb,Lc,Ld) [1]=(Lp,Lq,Hp,Hq) [2]=(Ha,Hb,Hc,Hd)
__device__ float4 g_agg[NBLK][3];
__device__ int    g_flag[NBLK];    // statically zero-init; self-resetting per replay
__device__ int    g_cnt[NBLK];     // read-counters; self-resetting per replay

struct Map { float a, b, c, d, p, q; };   // s -> [a b; c d] s + (p,q)

__device__ __forceinline__ Map mapIdent() { Map m = {1.f,0.f,0.f,1.f,0.f,0.f}; return m; }
// hi applied AFTER lo
__device__ __forceinline__ Map mapCompose(const Map& hi, const Map& lo) {
    Map r;
    r.a = fmaf(hi.a, lo.a, hi.b * lo.c);
    r.b = fmaf(hi.a, lo.b, hi.b * lo.d);
    r.c = fmaf(hi.c, lo.a, hi.d * lo.c);
    r.d = fmaf(hi.c, lo.b, hi.d * lo.d);
    r.p = fmaf(hi.a, lo.p, fmaf(hi.b, lo.q, hi.p));
    r.q = fmaf(hi.c, lo.p, fmaf(hi.d, lo.q, hi.q));
    return r;
}
__device__ __forceinline__ float2 mapApply(const Map& m, float vx, float vy) {
    return make_float2(fmaf(m.a, vx, fmaf(m.b, vy, m.p)),
                       fmaf(m.c, vx, fmaf(m.d, vy, m.q)));
}
__device__ __forceinline__ Map mapShflUp(const Map& m, int d) {
    Map r;
    r.a = __shfl_up_sync(0xffffffffu, m.a, d);
    r.b = __shfl_up_sync(0xffffffffu, m.b, d);
    r.c = __shfl_up_sync(0xffffffffu, m.c, d);
    r.d = __shfl_up_sync(0xffffffffu, m.d, d);
    r.p = __shfl_up_sync(0xffffffffu, m.p, d);
    r.q = __shfl_up_sync(0xffffffffu, m.q, d);
    return r;
}

// packed biquad step (both filters in one f32x2 lane pair): y0 = yL - yH
#define BSTEP2(xk, ok) {                                         \
    u64 xk2 = pack2((xk), (xk));                                 \
    u64 ff  = fma2(cb0, xk2, fma2(cb1, xm1p, mul2(cb2, xm2p))); \
    u64 yy  = fma2(cn1, s1p, fma2(cn2, s2p, ff));                \
    float yL, yH; unpack2(yy, yL, yH);                           \
    (ok) = yL - yH;                                              \
    s2p = s1p; s1p = yy; xm2p = xm1p; xm1p = xk2; }

// packed homogeneous correction step: y = y0 + c - d
#define CSTEP2(y0v, ov) {                                        \
    u64 cd = fma2(cn1, cd1, mul2(cn2, cd2));                     \
    float cc, dd; unpack2(cd, cc, dd);                           \
    (ov) = ((y0v) + cc) - dd;                                    \
    cd2 = cd1; cd1 = cd; }

__global__ __launch_bounds__(BT, 5)
void fused_kernel(const float* __restrict__ x, float* __restrict__ out,
                  const int* __restrict__ sr_p,
                  const float* __restrict__ cl_p,
                  const float* __restrict__ ch_p) {
    __shared__ float  sbuf[TILE];
    __shared__ float  scoef[10];
    __shared__ float4 sAE[2];            // [0]=(uL,vL,uH,vH)@n=END-1  [1]=@n=END-2
    __shared__ Map    sWarpL[NW], sWarpH[NW], sExclL[NW], sExclH[NW];
    __shared__ float4 sPred[WIN][3];
    __shared__ float4 sVin;

    int t   = threadIdx.x;
    int bid = blockIdx.x;

    // ---- stage tile coalesced ----
    size_t base4 = (size_t)bid * F4PB;
    const float4* xg4 = (const float4*)x;
    float4* s4 = (float4*)sbuf;
#pragma unroll
    for (int i = 0; i < F4PB / BT; i++) {
        size_t idx = base4 + t + (size_t)i * BT;
        if (idx < TOTAL_F4) s4[t + i * BT] = xg4[idx];
    }

    // ---- thread 0: coefficients ----
    if (t == 0) {
        int iv = *sr_p;
        float sr = (iv > 0 && iv < 100000000) ? (float)iv : __int_as_float(iv);
        const float Q = 0.707f;
        {
            float w0 = 2.0f * 3.14159265358979323846f * (*cl_p) / sr;
            float c  = cosf(w0);
            float al = sinf(w0) / (2.0f * Q);
            float a0 = 1.0f + al;
            scoef[0] = ((1.0f - c) * 0.5f) / a0;
            scoef[1] = (1.0f - c) / a0;
            scoef[2] = scoef[0];
            scoef[3] = (-2.0f * c) / a0;
            scoef[4] = (1.0f - al) / a0;
        }
        {
            float w0 = 2.0f * 3.14159265358979323846f * (*ch_p) / sr;
            float c  = cosf(w0);
            float al = sinf(w0) / (2.0f * Q);
            float a0 = 1.0f + al;
            scoef[5] = ((1.0f + c) * 0.5f) / a0;
            scoef[6] = -(1.0f + c) / a0;
            scoef[7] = scoef[5];
            scoef[8] = (-2.0f * c) / a0;
            scoef[9] = (1.0f - al) / a0;
        }
    }
    __syncthreads();

    float bL0 = scoef[0], bL1 = scoef[1], bL2 = scoef[2];
    float nL1 = -scoef[3], nL2 = -scoef[4];
    float bH0 = scoef[5], bH1 = scoef[6], bH2 = scoef[7];
    float nH1 = -scoef[8], nH2 = -scoef[9];

    // packed coefficient pairs (L in lane0, H in lane1)
    u64 cb0 = pack2(bL0, bH0), cb1 = pack2(bL1, bH1), cb2 = pack2(bL2, bH2);
    u64 cn1 = pack2(nL1, nH1), cn2 = pack2(nL2, nH2);

    int  g       = bid * BT + t;
    bool valid   = g < NCHUNK_TOT;
    bool resetCk = valid && (g % NCHUNK_CH) == 0;   // chunk is channel start

    // FIR history — must be read by ALL threads before pass A overwrites smem
    float hx1 = 0.f, hx2 = 0.f;
    if (valid && !resetCk) {
        if (t == 0) {
            size_t s0 = (size_t)g * CHUNK;
            hx1 = x[s0 - 1];
            hx2 = x[s0 - 2];
        } else {
            hx1 = sbuf[t * CHUNK - 1];
            hx2 = sbuf[t * CHUNK - 2];
        }
    }
    __syncthreads();   // history reads complete before in-place y0 writes

    // ---- A^CHUNK end states (threads 0-3, one homogeneous basis each) ----
    if (t < 4) {
        float na1 = (t < 2) ? nL1 : nH1;
        float na2 = (t < 2) ? nL2 : nH2;
        float y1 = (t & 1) ? 0.f : 1.f;
        float y2 = (t & 1) ? 1.f : 0.f;
#pragma unroll 1
        for (int n = 0; n < CHUNK; n++) {
            float y = fmaf(na1, y1, na2 * y2);
            y2 = y1; y1 = y;
        }
        ((float*)&sAE[0])[t] = y1;   // y[CHUNK-1]
        ((float*)&sAE[1])[t] = y2;   // y[CHUNK-2]
    }

    // ---- pass A: zero-init packed recurrence, write y0 in place ----
    float l1, l2, h1, h2;
    {
        u64 s1p = pack2(0.f, 0.f), s2p = s1p;
        u64 xm1p = pack2(hx1, hx1), xm2p = pack2(hx2, hx2);
        if (valid) {
            float* cb = sbuf + t * CHUNK;
            float4 xv = *reinterpret_cast<const float4*>(cb);
#pragma unroll 1
            for (int k = 0; k < CHUNK - 4; k += 4) {
                float4 nx = *reinterpret_cast<const float4*>(cb + k + 4);
                float4 ov;
                BSTEP2(xv.x, ov.x);
                BSTEP2(xv.y, ov.y);
                BSTEP2(xv.z, ov.z);
                BSTEP2(xv.w, ov.w);
                *reinterpret_cast<float4*>(cb + k) = ov;
                xv = nx;
            }
            float4 ov;
            BSTEP2(xv.x, ov.x);
            BSTEP2(xv.y, ov.y);
            BSTEP2(xv.z, ov.z);
            BSTEP2(xv.w, ov.w);
            *reinterpret_cast<float4*>(cb + CHUNK - 4) = ov;
        }
        unpack2(s1p, l1, h1);
        unpack2(s2p, l2, h2);
    }
    __syncthreads();

    float4 tE1 = sAE[0];
    float4 tE2 = sAE[1];

    // ---- per-chunk affine maps (interleaved L/H scan) ----
    Map mL, mH;
    if (!valid) { mL = mapIdent(); mH = mapIdent(); }
    else if (resetCk) {
        mL.a = mL.b = mL.c = mL.d = 0.f; mL.p = l1; mL.q = l2;
        mH.a = mH.b = mH.c = mH.d = 0.f; mH.p = h1; mH.q = h2;
    } else {
        mL.a = tE1.x; mL.b = tE1.y; mL.c = tE2.x; mL.d = tE2.y; mL.p = l1; mL.q = l2;
        mH.a = tE1.z; mH.b = tE1.w; mH.c = tE2.z; mH.d = tE2.w; mH.p = h1; mH.q = h2;
    }

    int lane = t & 31, w = t >> 5;
#pragma unroll
    for (int off = 1; off < 32; off <<= 1) {
        Map pL = mapShflUp(mL, off);
        Map pH = mapShflUp(mH, off);
        if (lane >= off) { mL = mapCompose(mL, pL); mH = mapCompose(mH, pH); }
    }
    if (lane == 31) { sWarpL[w] = mL; sWarpH[w] = mH; }
    __syncthreads();

    // ---- block aggregate + IMMEDIATE publish ----
    if (t == 0) {
        Map eL = mapIdent(), eH = mapIdent();
#pragma unroll
        for (int i = 0; i < NW; i++) {
            sExclL[i] = eL; sExclH[i] = eH;
            eL = mapCompose(sWarpL[i], eL);
            eH = mapCompose(sWarpH[i], eH);
        }
        __stcg(&g_agg[bid][0], make_float4(eL.a, eL.b, eL.c, eL.d));
        __stcg(&g_agg[bid][1], make_float4(eL.p, eL.q, eH.p, eH.q));
        __stcg(&g_agg[bid][2], make_float4(eH.a, eH.b, eH.c, eH.d));
        __threadfence();
        atomicExch(&g_flag[bid], 1);
    }

    // ---- parallel-window look-back (warp 0) + flag recycling ----
    if (w == 0) {
        int pred = bid - 1 - t;
        if (t < WIN && pred >= 0) {
            while (__ldcg(&g_flag[pred]) == 0) __nanosleep(64);
            __threadfence();
            sPred[t][0] = __ldcg(&g_agg[pred][0]);
            sPred[t][1] = __ldcg(&g_agg[pred][1]);
            sPred[t][2] = __ldcg(&g_agg[pred][2]);
            // flag recycling: last of R readers resets flag+cnt for next replay
            int R = (NBLK - 1 - pred < WIN) ? (NBLK - 1 - pred) : WIN;
            int old = atomicAdd(&g_cnt[pred], 1);
            if (old == R - 1) {
                __stcg(&g_cnt[pred], 0);
                __stcg(&g_flag[pred], 0);
            }
        }
        __syncwarp();
        if (t == 0) {
            float4 vin = make_float4(0.f, 0.f, 0.f, 0.f);
            if (bid > 0) {
                int nAvail = (bid < WIN) ? bid : WIN;
                int term = nAvail - 1;
                for (int i = 0; i < nAvail; i++) {
                    float4 fL = sPred[i][0];
                    float4 fH = sPred[i][2];
                    if (fL.x == 0.f && fL.y == 0.f && fL.z == 0.f && fL.w == 0.f &&
                        fH.x == 0.f && fH.y == 0.f && fH.z == 0.f && fH.w == 0.f) {
                        term = i;
                        break;
                    }
                }
                float4 off0 = sPred[term][1];
                float sLx = off0.x, sLy = off0.y, sHx = off0.z, sHy = off0.w;
                for (int i = term - 1; i >= 0; i--) {
                    float4 fL = sPred[i][0];
                    float4 fH = sPred[i][2];
                    float4 fo = sPred[i][1];
                    float nLx = fmaf(fL.x, sLx, fmaf(fL.y, sLy, fo.x));
                    float nLy = fmaf(fL.z, sLx, fmaf(fL.w, sLy, fo.y));
                    float nHx = fmaf(fH.x, sHx, fmaf(fH.y, sHy, fo.z));
                    float nHy = fmaf(fH.z, sHx, fmaf(fH.w, sHy, fo.w));
                    sLx = nLx; sLy = nLy; sHx = nHx; sHy = nHy;
                }
                vin = make_float4(sLx, sLy, sHx, sHy);
            }
            sVin = vin;
        }
    }
    __syncthreads();
    float4 vin = sVin;

    // thread-exclusive map within block
    Map exL = mapShflUp(mL, 1);
    Map exH = mapShflUp(mH, 1);
    if (lane == 0) { exL = mapIdent(); exH = mapIdent(); }
    exL = mapCompose(exL, sExclL[w]);
    exH = mapCompose(exH, sExclH[w]);

    // exact initial state for this chunk
    float2 sL = resetCk ? make_float2(0.f, 0.f) : mapApply(exL, vin.x, vin.y);
    float2 sH = resetCk ? make_float2(0.f, 0.f) : mapApply(exH, vin.z, vin.w);

    // ---- correction pass (packed): y = y0 + c - d ----
    if (valid) {
        u64 cd1 = pack2(sL.x, sH.x);
        u64 cd2 = pack2(sL.y, sH.y);
        float* cb = sbuf + t * CHUNK;
        float4 yv = *reinterpret_cast<const float4*>(cb);
#pragma unroll 1
        for (int k = 0; k < CHUNK - 4; k += 4) {
            float4 ny = *reinterpret_cast<const float4*>(cb + k + 4);
            float4 ov;
            CSTEP2(yv.x, ov.x);
            CSTEP2(yv.y, ov.y);
            CSTEP2(yv.z, ov.z);
            CSTEP2(yv.w, ov.w);
            *reinterpret_cast<float4*>(cb + k) = ov;
            yv = ny;
        }
        float4 ov;
        CSTEP2(yv.x, ov.x);
        CSTEP2(yv.y, ov.y);
        CSTEP2(yv.z, ov.z);
        CSTEP2(yv.w, ov.w);
        *reinterpret_cast<float4*>(cb + CHUNK - 4) = ov;
    }
    __syncthreads();

    // ---- coalesced store ----
    float4* og4 = (float4*)out;
#pragma unroll
    for (int i = 0; i < F4PB / BT; i++) {
        size_t idx = base4 + t + (size_t)i * BT;
        if (idx < TOTAL_F4) og4[idx] = s4[t + i * BT];
    }
}

extern "C" void kernel_launch(void* const* d_in, const int* in_sizes, int n_in,
                              void* d_out, int out_size) {
    const float* audio = (const float*)d_in[0];
    const int*   sr    = (const int*)d_in[1];
    const float* cl    = (const float*)d_in[2];
    const float* ch    = (const float*)d_in[3];
    float* out = (float*)d_out;

    fused_kernel<<<NBLK, BT>>>(audio, out, sr, cl, ch);
}

// round 13
// speedup vs baseline: 1.4169x; 1.0617x over previous
#include <cuda_runtime.h>
#include <math.h>

#define T_LEN      220500
#define NCH        64
#define CHUNK      84
#define NCHUNK_CH  2625                // 220500 / 84
#define NCHUNK_TOT 168000              // 64 * 2625
#define TOTAL_F4   3528000             // 14,112,000 / 4
#define BT         128
#define NW         (BT / 32)
#define TILE       (BT * CHUNK)        // 10752 floats = 43008 B
#define F4PB       (TILE / 4)          // 2688
#define NBLK       ((NCHUNK_TOT + BT - 1) / BT)   // 1313
#define WIN        21                  // reset-block gap is exactly 20-21

typedef unsigned long long u64;

// ---- packed f32x2 helpers (sm_103a FFMA2 path) ----
__device__ __forceinline__ u64 fma2(u64 a, u64 b, u64 c) {
    u64 d; asm("fma.rn.f32x2 %0, %1, %2, %3;" : "=l"(d) : "l"(a), "l"(b), "l"(c)); return d;
}
__device__ __forceinline__ u64 mul2(u64 a, u64 b) {
    u64 d; asm("mul.rn.f32x2 %0, %1, %2;" : "=l"(d) : "l"(a), "l"(b)); return d;
}
__device__ __forceinline__ u64 pack2(float lo, float hi) {
    u64 d; asm("mov.b64 %0, {%1, %2};" : "=l"(d) : "f"(lo), "f"(hi)); return d;
}
__device__ __forceinline__ void unpack2(u64 v, float& lo, float& hi) {
    asm("mov.b64 {%0, %1}, %2;" : "=f"(lo), "=f"(hi) : "l"(v));
}

// published per-block aggregate: [0]=(La,Lb,Lc,Ld) [1]=(Lp,Lq,Hp,Hq) [2]=(Ha,Hb,Hc,Hd)
__device__ float4 g_agg[NBLK][3];
__device__ int    g_flag[NBLK];    // statically zero-init; self-resetting per replay
__device__ int    g_cnt[NBLK];     // read-counters; self-resetting per replay

struct Map { float a, b, c, d, p, q; };   // s -> [a b; c d] s + (p,q)

__device__ __forceinline__ Map mapIdent() { Map m = {1.f,0.f,0.f,1.f,0.f,0.f}; return m; }
// hi applied AFTER lo
__device__ __forceinline__ Map mapCompose(const Map& hi, const Map& lo) {
    Map r;
    r.a = fmaf(hi.a, lo.a, hi.b * lo.c);
    r.b = fmaf(hi.a, lo.b, hi.b * lo.d);
    r.c = fmaf(hi.c, lo.a, hi.d * lo.c);
    r.d = fmaf(hi.c, lo.b, hi.d * lo.d);
    r.p = fmaf(hi.a, lo.p, fmaf(hi.b, lo.q, hi.p));
    r.q = fmaf(hi.c, lo.p, fmaf(hi.d, lo.q, hi.q));
    return r;
}
__device__ __forceinline__ float2 mapApply(const Map& m, float vx, float vy) {
    return make_float2(fmaf(m.a, vx, fmaf(m.b, vy, m.p)),
                       fmaf(m.c, vx, fmaf(m.d, vy, m.q)));
}
__device__ __forceinline__ Map mapShflUp(const Map& m, int d) {
    Map r;
    r.a = __shfl_up_sync(0xffffffffu, m.a, d);
    r.b = __shfl_up_sync(0xffffffffu, m.b, d);
    r.c = __shfl_up_sync(0xffffffffu, m.c, d);
    r.d = __shfl_up_sync(0xffffffffu, m.d, d);
    r.p = __shfl_up_sync(0xffffffffu, m.p, d);
    r.q = __shfl_up_sync(0xffffffffu, m.q, d);
    return r;
}

// packed biquad step (both filters in one f32x2 lane pair): y0 = yL - yH
#define BSTEP2(xk, ok) {                                         \
    u64 xk2 = pack2((xk), (xk));                                 \
    u64 ff  = fma2(cb0, xk2, fma2(cb1, xm1p, mul2(cb2, xm2p))); \
    u64 yy  = fma2(cn1, s1p, fma2(cn2, s2p, ff));                \
    float yL, yH; unpack2(yy, yL, yH);                           \
    (ok) = yL - yH;                                              \
    s2p = s1p; s1p = yy; xm2p = xm1p; xm1p = xk2; }

// packed homogeneous correction step: y = y0 + c - d
#define CSTEP2(y0v, ov) {                                        \
    u64 cd = fma2(cn1, cd1, mul2(cn2, cd2));                     \
    float cc, dd; unpack2(cd, cc, dd);                           \
    (ov) = ((y0v) + cc) - dd;                                    \
    cd2 = cd1; cd1 = cd; }

__global__ __launch_bounds__(BT, 5)
void fused_kernel(const float* __restrict__ x, float* __restrict__ out,
                  const int* __restrict__ sr_p,
                  const float* __restrict__ cl_p,
                  const float* __restrict__ ch_p) {
    __shared__ float  sbuf[TILE];
    __shared__ float  scoef[10];
    __shared__ float4 sAE[2];            // [0]=(uL,vL,uH,vH)@n=END-1  [1]=@n=END-2
    __shared__ Map    sWarpL[NW], sWarpH[NW], sExclL[NW], sExclH[NW];
    __shared__ float4 sPred[WIN][3];
    __shared__ float4 sVin;

    int t   = threadIdx.x;
    int bid = blockIdx.x;
    bool fullBlk = (bid < NBLK - 1);     // all but last block are fully valid

    // ---- stage tile coalesced (unguarded fast path) ----
    size_t base4 = (size_t)bid * F4PB;
    const float4* xg4 = (const float4*)x;
    float4* s4 = (float4*)sbuf;
    if (fullBlk) {
#pragma unroll
        for (int i = 0; i < F4PB / BT; i++)
            s4[t + i * BT] = xg4[base4 + t + (size_t)i * BT];
    } else {
#pragma unroll
        for (int i = 0; i < F4PB / BT; i++) {
            size_t idx = base4 + t + (size_t)i * BT;
            if (idx < TOTAL_F4) s4[t + i * BT] = xg4[idx];
        }
    }

    // ---- thread 0: coefficients ----
    if (t == 0) {
        int iv = *sr_p;
        float sr = (iv > 0 && iv < 100000000) ? (float)iv : __int_as_float(iv);
        const float Q = 0.707f;
        {
            float w0 = 2.0f * 3.14159265358979323846f * (*cl_p) / sr;
            float c  = cosf(w0);
            float al = sinf(w0) / (2.0f * Q);
            float a0 = 1.0f + al;
            scoef[0] = ((1.0f - c) * 0.5f) / a0;
            scoef[1] = (1.0f - c) / a0;
            scoef[2] = scoef[0];
            scoef[3] = (-2.0f * c) / a0;
            scoef[4] = (1.0f - al) / a0;
        }
        {
            float w0 = 2.0f * 3.14159265358979323846f * (*ch_p) / sr;
            float c  = cosf(w0);
            float al = sinf(w0) / (2.0f * Q);
            float a0 = 1.0f + al;
            scoef[5] = ((1.0f + c) * 0.5f) / a0;
            scoef[6] = -(1.0f + c) / a0;
            scoef[7] = scoef[5];
            scoef[8] = (-2.0f * c) / a0;
            scoef[9] = (1.0f - al) / a0;
        }
    }
    __syncthreads();

    float bL0 = scoef[0], bL1 = scoef[1], bL2 = scoef[2];
    float nL1 = -scoef[3], nL2 = -scoef[4];
    float bH0 = scoef[5], bH1 = scoef[6], bH2 = scoef[7];
    float nH1 = -scoef[8], nH2 = -scoef[9];

    // packed coefficient pairs (L in lane0, H in lane1)
    u64 cb0 = pack2(bL0, bH0), cb1 = pack2(bL1, bH1), cb2 = pack2(bL2, bH2);
    u64 cn1 = pack2(nL1, nH1), cn2 = pack2(nL2, nH2);

    int  g       = bid * BT + t;
    bool valid   = g < NCHUNK_TOT;
    bool resetCk = valid && (g % NCHUNK_CH) == 0;   // chunk is channel start

    // FIR history — must be read by ALL threads before pass A overwrites smem
    float hx1 = 0.f, hx2 = 0.f;
    if (valid && !resetCk) {
        if (t == 0) {
            size_t s0 = (size_t)g * CHUNK;
            hx1 = x[s0 - 1];
            hx2 = x[s0 - 2];
        } else {
            hx1 = sbuf[t * CHUNK - 1];
            hx2 = sbuf[t * CHUNK - 2];
        }
    }
    __syncthreads();   // history reads complete before in-place y0 writes

    // ---- A^CHUNK end states (threads 0-3, one homogeneous basis each) ----
    if (t < 4) {
        float na1 = (t < 2) ? nL1 : nH1;
        float na2 = (t < 2) ? nL2 : nH2;
        float y1 = (t & 1) ? 0.f : 1.f;
        float y2 = (t & 1) ? 1.f : 0.f;
#pragma unroll 1
        for (int n = 0; n < CHUNK; n++) {
            float y = fmaf(na1, y1, na2 * y2);
            y2 = y1; y1 = y;
        }
        ((float*)&sAE[0])[t] = y1;   // y[CHUNK-1]
        ((float*)&sAE[1])[t] = y2;   // y[CHUNK-2]
    }

    // ---- pass A: zero-init packed recurrence, write y0 in place ----
    float l1, l2, h1, h2;
    {
        u64 s1p = pack2(0.f, 0.f), s2p = s1p;
        u64 xm1p = pack2(hx1, hx1), xm2p = pack2(hx2, hx2);
        if (valid) {
            float* cb = sbuf + t * CHUNK;
#pragma unroll 7
            for (int k = 0; k < CHUNK; k += 4) {
                float4 xv = *reinterpret_cast<const float4*>(cb + k);
                float4 ov;
                BSTEP2(xv.x, ov.x);
                BSTEP2(xv.y, ov.y);
                BSTEP2(xv.z, ov.z);
                BSTEP2(xv.w, ov.w);
                *reinterpret_cast<float4*>(cb + k) = ov;
            }
        }
        unpack2(s1p, l1, h1);
        unpack2(s2p, l2, h2);
    }
    __syncthreads();

    float4 tE1 = sAE[0];
    float4 tE2 = sAE[1];

    // ---- per-chunk affine maps (interleaved L/H scan) ----
    Map mL, mH;
    if (!valid) { mL = mapIdent(); mH = mapIdent(); }
    else if (resetCk) {
        mL.a = mL.b = mL.c = mL.d = 0.f; mL.p = l1; mL.q = l2;
        mH.a = mH.b = mH.c = mH.d = 0.f; mH.p = h1; mH.q = h2;
    } else {
        mL.a = tE1.x; mL.b = tE1.y; mL.c = tE2.x; mL.d = tE2.y; mL.p = l1; mL.q = l2;
        mH.a = tE1.z; mH.b = tE1.w; mH.c = tE2.z; mH.d = tE2.w; mH.p = h1; mH.q = h2;
    }

    int lane = t & 31, w = t >> 5;
#pragma unroll
    for (int off = 1; off < 32; off <<= 1) {
        Map pL = mapShflUp(mL, off);
        Map pH = mapShflUp(mH, off);
        if (lane >= off) { mL = mapCompose(mL, pL); mH = mapCompose(mH, pH); }
    }
    if (lane == 31) { sWarpL[w] = mL; sWarpH[w] = mH; }
    __syncthreads();

    // ---- block aggregate + IMMEDIATE publish ----
    if (t == 0) {
        Map eL = mapIdent(), eH = mapIdent();
#pragma unroll
        for (int i = 0; i < NW; i++) {
            sExclL[i] = eL; sExclH[i] = eH;
            eL = mapCompose(sWarpL[i], eL);
            eH = mapCompose(sWarpH[i], eH);
        }
        __stcg(&g_agg[bid][0], make_float4(eL.a, eL.b, eL.c, eL.d));
        __stcg(&g_agg[bid][1], make_float4(eL.p, eL.q, eH.p, eH.q));
        __stcg(&g_agg[bid][2], make_float4(eH.a, eH.b, eH.c, eH.d));
        __threadfence();
        atomicExch(&g_flag[bid], 1);
    }

    // ---- parallel-window look-back (warp 0) + flag recycling ----
    if (w == 0) {
        int pred = bid - 1 - t;
        if (t < WIN && pred >= 0) {
            while (__ldcg(&g_flag[pred]) == 0) __nanosleep(64);
            __threadfence();
            sPred[t][0] = __ldcg(&g_agg[pred][0]);
            sPred[t][1] = __ldcg(&g_agg[pred][1]);
            sPred[t][2] = __ldcg(&g_agg[pred][2]);
            // flag recycling: last of R readers resets flag+cnt for next replay
            int R = (NBLK - 1 - pred < WIN) ? (NBLK - 1 - pred) : WIN;
            int old = atomicAdd(&g_cnt[pred], 1);
            if (old == R - 1) {
                __stcg(&g_cnt[pred], 0);
                __stcg(&g_flag[pred], 0);
            }
        }
        __syncwarp();
        if (t == 0) {
            float4 vin = make_float4(0.f, 0.f, 0.f, 0.f);
            if (bid > 0) {
                int nAvail = (bid < WIN) ? bid : WIN;
                int term = nAvail - 1;
                for (int i = 0; i < nAvail; i++) {
                    float4 fL = sPred[i][0];
                    float4 fH = sPred[i][2];
                    if (fL.x == 0.f && fL.y == 0.f && fL.z == 0.f && fL.w == 0.f &&
                        fH.x == 0.f && fH.y == 0.f && fH.z == 0.f && fH.w == 0.f) {
                        term = i;
                        break;
                    }
                }
                float4 off0 = sPred[term][1];
                float sLx = off0.x, sLy = off0.y, sHx = off0.z, sHy = off0.w;
                for (int i = term - 1; i >= 0; i--) {
                    float4 fL = sPred[i][0];
                    float4 fH = sPred[i][2];
                    float4 fo = sPred[i][1];
                    float nLx = fmaf(fL.x, sLx, fmaf(fL.y, sLy, fo.x));
                    float nLy = fmaf(fL.z, sLx, fmaf(fL.w, sLy, fo.y));
                    float nHx = fmaf(fH.x, sHx, fmaf(fH.y, sHy, fo.z));
                    float nHy = fmaf(fH.z, sHx, fmaf(fH.w, sHy, fo.w));
                    sLx = nLx; sLy = nLy; sHx = nHx; sHy = nHy;
                }
                vin = make_float4(sLx, sLy, sHx, sHy);
            }
            sVin = vin;
        }
    }
    __syncthreads();
    float4 vin = sVin;

    // thread-exclusive map within block
    Map exL = mapShflUp(mL, 1);
    Map exH = mapShflUp(mH, 1);
    if (lane == 0) { exL = mapIdent(); exH = mapIdent(); }
    exL = mapCompose(exL, sExclL[w]);
    exH = mapCompose(exH, sExclH[w]);

    // exact initial state for this chunk
    float2 sL = resetCk ? make_float2(0.f, 0.f) : mapApply(exL, vin.x, vin.y);
    float2 sH = resetCk ? make_float2(0.f, 0.f) : mapApply(exH, vin.z, vin.w);

    // ---- correction pass (packed): y = y0 + c - d ----
    if (valid) {
        u64 cd1 = pack2(sL.x, sH.x);
        u64 cd2 = pack2(sL.y, sH.y);
        float* cb = sbuf + t * CHUNK;
#pragma unroll 7
        for (int k = 0; k < CHUNK; k += 4) {
            float4 yv = *reinterpret_cast<const float4*>(cb + k);
            float4 ov;
            CSTEP2(yv.x, ov.x);
            CSTEP2(yv.y, ov.y);
            CSTEP2(yv.z, ov.z);
            CSTEP2(yv.w, ov.w);
            *reinterpret_cast<float4*>(cb + k) = ov;
        }
    }
    __syncthreads();

    // ---- coalesced store (unguarded fast path) ----
    float4* og4 = (float4*)out;
    if (fullBlk) {
#pragma unroll
        for (int i = 0; i < F4PB / BT; i++)
            og4[base4 + t + (size_t)i * BT] = s4[t + i * BT];
    } else {
#pragma unroll
        for (int i = 0; i < F4PB / BT; i++) {
            size_t idx = base4 + t + (size_t)i * BT;
            if (idx < TOTAL_F4) og4[idx] = s4[t + i * BT];
        }
    }
}

extern "C" void kernel_launch(void* const* d_in, const int* in_sizes, int n_in,
                              void* d_out, int out_size) {
    const float* audio = (const float*)d_in[0];
    const int*   sr    = (const int*)d_in[1];
    const float* cl    = (const float*)d_in[2];
    const float* ch    = (const float*)d_in[3];
    float* out = (float*)d_out;

    fused_kernel<<<NBLK, BT>>>(audio, out, sr, cl, ch);
}